// round 11
// baseline (speedup 1.0000x reference)
#include <cuda_runtime.h>
#include <cuda_fp16.h>
#include <math.h>
#include <stdint.h>

// Qwen3 MoE gate — hybrid: tensor CTAs (3-pass split-FP16 mma.sync, R9 path)
// + fp32 FFMA2 CTAs (exact fp32 GEMM) running concurrently, since HMMA
// throughput is a hard per-SM-pair cap (~49% pipe) while fp32 pipes idle.
// Per 69 blockIdx: 49 tensor (64 tok) + 20 fp32 (48 tok). Grid 276 (1 wave).
// Output: [idx f32 (T*8) | weights (T*8)].

#define HDIM 2048
#define NEXP 128
#define TOPK 8
#define NTHR 128

// ---- tensor role ----
#define BM   64
#define BK   64
#define NCH  (HDIM / BK)          // 32
#define XTILE_B  (BM * 128)
#define WTILE_B  (NEXP * 128)
#define OFF_XH   0
#define OFF_XL   XTILE_B
#define OFF_WH   (2 * XTILE_B)
#define OFF_WL   (2 * XTILE_B + WTILE_B)
#define STAGE_B  (2 * XTILE_B + 2 * WTILE_B)   // 48KB
#define SMEM_TOT (2 * STAGE_B)                 // 96KB

// ---- fp32 role ----
#define FM    48                  // tokens per fp32 CTA
#define FBK   16
#define FNCH  (HDIM / FBK)        // 128
#define FXS(s) ((s) * 4096)                    // xs: [16][64] f32 (padded slots)
#define FWS(s) (8192 + (s) * 8192)             // ws: [16][128] f32

// ---- role split ----
#define NT_PER 49
#define NF_PER 20
#define PERIOD 69
#define NGROUP 4                  // grid = 4*69 = 276
#define NT_TOT (NT_PER * NGROUP)  // 196 tensor CTAs
#define TENSOR_TOKENS (NT_TOT * BM)  // 12544

__device__ __half g_wh[NEXP * HDIM];
__device__ __half g_wl[NEXP * HDIM];

__device__ __forceinline__ uint32_t smem_u32(const void* p) {
    uint32_t a;
    asm("{ .reg .u64 t; cvta.to.shared.u64 t, %1; cvt.u32.u64 %0, t; }"
        : "=r"(a) : "l"(p));
    return a;
}

#define SWZ(o) ((o) ^ ((((uint32_t)(o)) >> 3) & 0x70))

#define CP16(dst, src) \
    asm volatile("cp.async.cg.shared.global [%0], [%1], 16;" \
                 :: "r"(dst), "l"(src))
#define CP_COMMIT() asm volatile("cp.async.commit_group;" ::: "memory")
#define CP_WAIT0()  asm volatile("cp.async.wait_group 0;" ::: "memory")

#define LDM4(R, a) \
    asm volatile("ldmatrix.sync.aligned.m8n8.x4.shared.b16 {%0,%1,%2,%3}, [%4];" \
                 : "=r"((R)[0]), "=r"((R)[1]), "=r"((R)[2]), "=r"((R)[3])      \
                 : "r"(a))

#define MMA(d, a, b0, b1) \
    asm volatile("mma.sync.aligned.m16n8k16.row.col.f32.f16.f16.f32 "          \
                 "{%0,%1,%2,%3}, {%4,%5,%6,%7}, {%8,%9}, {%0,%1,%2,%3};"       \
                 : "+f"((d)[0]), "+f"((d)[1]), "+f"((d)[2]), "+f"((d)[3])      \
                 : "r"((a)[0]), "r"((a)[1]), "r"((a)[2]), "r"((a)[3]),         \
                   "r"(b0), "r"(b1))

#define MMAH(d, a, b0, b1) \
    asm volatile("mma.sync.aligned.m16n8k16.row.col.f16.f16.f16.f16 "          \
                 "{%0,%1}, {%2,%3,%4,%5}, {%6,%7}, {%0,%1};"                   \
                 : "+r"((d)[0]), "+r"((d)[1])                                  \
                 : "r"((a)[0]), "r"((a)[1]), "r"((a)[2]), "r"((a)[3]),         \
                   "r"(b0), "r"(b1))

#define FMA2(c, a, b) asm("fma.rn.f32x2 %0, %1, %2, %0;" : "+l"(c) : "l"(a), "l"(b))
#define PACK2(d, s)   asm("mov.b64 %0, {%1, %1};" : "=l"(d) : "f"(s))
#define UNPACK2(lo, hi, s) asm("mov.b64 {%0, %1}, %2;" : "=f"(lo), "=f"(hi) : "l"(s))

__device__ __forceinline__ uint32_t pack_h2(float a, float b) {
    __half2 h = __floats2half2_rn(a, b);
    return *(uint32_t*)&h;
}

// -------- prep: split W into fp16 hi + (lo * 2048) --------
__global__ void prep_w_kernel(const float* __restrict__ w) {
    int i = blockIdx.x * blockDim.x + threadIdx.x;
    float4 v = ((const float4*)w)[i];
    float hx = __half2float(__float2half_rn(v.x));
    float hy = __half2float(__float2half_rn(v.y));
    float hz = __half2float(__float2half_rn(v.z));
    float hw = __half2float(__float2half_rn(v.w));
    uint2 hi, lo;
    hi.x = pack_h2(hx, hy);
    hi.y = pack_h2(hz, hw);
    lo.x = pack_h2((v.x - hx) * 2048.0f, (v.y - hy) * 2048.0f);
    lo.y = pack_h2((v.z - hz) * 2048.0f, (v.w - hw) * 2048.0f);
    ((uint2*)g_wh)[i] = hi;
    ((uint2*)g_wl)[i] = lo;
}

// -------- shared epilogue: softmax / top-8 / renorm over one smem row --------
__device__ __forceinline__ void topk_scan(float* row, int token, int T,
                                          float* __restrict__ out) {
    float m0 = row[0];
#pragma unroll 8
    for (int c = 1; c < NEXP; c++) {
        float v = row[c];
        if (v > m0) m0 = v;
    }
    int   ids[TOPK];
    float wts[TOPK];
    float sum = 0.0f;
#pragma unroll
    for (int kk = 0; kk < TOPK; kk++) {
        float best = -INFINITY;
        int   bi   = 0;
#pragma unroll 8
        for (int c = 0; c < NEXP; c++) {
            float v = row[c];
            if (v > best) { best = v; bi = c; }     // ties -> lowest index
        }
        row[bi] = -INFINITY;
        ids[kk] = bi;
        float e = expf(best - m0);
        wts[kk] = e;
        sum += e;
    }
    float* out_idx = out;
    float* out_wt  = out + (size_t)T * TOPK;
#pragma unroll
    for (int kk = 0; kk < TOPK; kk++) {
        out_idx[(size_t)token * TOPK + kk] = (float)ids[kk];
        out_wt [(size_t)token * TOPK + kk] = wts[kk] / sum;
    }
}

// -------- main hybrid kernel --------
__global__ __launch_bounds__(NTHR, 2)
void gate_kernel(const float* __restrict__ x, const float* __restrict__ w,
                 float* __restrict__ out, int T)
{
    extern __shared__ char smem[];
    const uint32_t sb = smem_u32(smem);
    const int tid  = threadIdx.x;
    const int lane = tid & 31;
    const int wid  = tid >> 5;

    const int grp = blockIdx.x / PERIOD;
    const int rem = blockIdx.x % PERIOD;

    if (rem < NT_PER) {
        // ================= TENSOR ROLE (R9 path) =================
        const int bm = (grp * NT_PER + rem) * BM;

        float    acc1[2][8][4];
        uint32_t acc2[2][8][2];
#pragma unroll
        for (int i = 0; i < 2; i++)
#pragma unroll
            for (int j = 0; j < 8; j++) {
#pragma unroll
                for (int r = 0; r < 4; r++) acc1[i][j][r] = 0.f;
                acc2[i][j][0] = 0u; acc2[i][j][1] = 0u;
            }

        int xrow[8];
#pragma unroll
        for (int j = 0; j < 8; j++) xrow[j] = (tid + j * NTHR) >> 4;
        const int xq = tid & 15;
        const float* xg = x + (size_t)bm * HDIM;

        int wrow[8];
#pragma unroll
        for (int j = 0; j < 8; j++) wrow[j] = (tid + j * NTHR) >> 3;
        const int ws = tid & 7;

        const int wm = (wid & 1) * 32;
        const int wn = (wid >> 1) * 64;
        const int aRow = (lane & 7) + ((lane >> 3) & 1) * 8;
        const int aKB  = ((lane >> 4) & 1) * 16;
        const int bRow = (lane & 7) + ((lane >> 4) & 1) * 8;
        const int bKB  = ((lane >> 3) & 1) * 16;

#define ISSUE_W(c, stg) do {                                                   \
    _Pragma("unroll")                                                          \
    for (int j = 0; j < 8; j++) {                                              \
        uint32_t o  = SWZ((uint32_t)(wrow[j] * 128 + ws * 16));                \
        const __half* sh = g_wh + (size_t)wrow[j] * HDIM + (c) * BK + ws * 8;  \
        const __half* sl = g_wl + (size_t)wrow[j] * HDIM + (c) * BK + ws * 8;  \
        CP16(sb + (stg) + OFF_WH + o, sh);                                     \
        CP16(sb + (stg) + OFF_WL + o, sl);                                     \
    }                                                                          \
    CP_COMMIT();                                                               \
} while (0)

#define LOAD_X(c, xr) do {                                                     \
    _Pragma("unroll")                                                          \
    for (int j = 0; j < 8; j++)                                                \
        xr[j] = *(const float4*)(xg + (size_t)xrow[j] * HDIM + (c) * BK + xq * 4); \
} while (0)

#define STORE_X(xr, stg) do {                                                  \
    _Pragma("unroll")                                                          \
    for (int j = 0; j < 8; j++) {                                              \
        float4 v = xr[j];                                                      \
        float hx = __half2float(__float2half_rn(v.x));                         \
        float hy = __half2float(__float2half_rn(v.y));                         \
        float hz = __half2float(__float2half_rn(v.z));                         \
        float hw = __half2float(__float2half_rn(v.w));                         \
        uint2 hi, lo;                                                          \
        hi.x = pack_h2(hx, hy);  hi.y = pack_h2(hz, hw);                       \
        lo.x = pack_h2((v.x - hx) * 2048.f, (v.y - hy) * 2048.f);              \
        lo.y = pack_h2((v.z - hz) * 2048.f, (v.w - hw) * 2048.f);              \
        uint32_t o = SWZ((uint32_t)(xrow[j] * 128 + xq * 8));                  \
        *(uint2*)(smem + (stg) + OFF_XH + o) = hi;                             \
        *(uint2*)(smem + (stg) + OFF_XL + o) = lo;                             \
    }                                                                          \
} while (0)

        {
            float4 xr[8];
            ISSUE_W(0, 0);
            LOAD_X(0, xr);
            STORE_X(xr, 0);
            CP_WAIT0();
            __syncthreads();
        }

        for (int c = 0; c < NCH; c++) {
            const uint32_t stg  = (uint32_t)((c & 1) ? STAGE_B : 0);
            const uint32_t nstg = stg ^ STAGE_B;
            float4 xr[8];
            if (c + 1 < NCH) {
                ISSUE_W(c + 1, nstg);
                LOAD_X(c + 1, xr);
            }

#pragma unroll
            for (int ks = 0; ks < 4; ks++) {
                uint32_t Ah[2][4], Al[2][4], Bh[4][4], Bl[4][4];
#pragma unroll
                for (int mt = 0; mt < 2; mt++) {
                    uint32_t o = SWZ((uint32_t)((wm + mt * 16 + aRow) * 128 + ks * 32 + aKB));
                    LDM4(Ah[mt], sb + stg + OFF_XH + o);
                    LDM4(Al[mt], sb + stg + OFF_XL + o);
                }
#pragma unroll
                for (int p = 0; p < 4; p++) {
                    uint32_t o = SWZ((uint32_t)((wn + p * 16 + bRow) * 128 + ks * 32 + bKB));
                    LDM4(Bh[p], sb + stg + OFF_WH + o);
                    LDM4(Bl[p], sb + stg + OFF_WL + o);
                }
#pragma unroll
                for (int mt = 0; mt < 2; mt++)
#pragma unroll
                    for (int nt = 0; nt < 8; nt++) {
                        const int p = nt >> 1, r0 = (nt & 1) * 2;
                        MMA (acc1[mt][nt], Ah[mt], Bh[p][r0], Bh[p][r0 + 1]);
                        MMAH(acc2[mt][nt], Al[mt], Bh[p][r0], Bh[p][r0 + 1]);
                        MMAH(acc2[mt][nt], Ah[mt], Bl[p][r0], Bl[p][r0 + 1]);
                    }
            }

            if (c + 1 < NCH) STORE_X(xr, nstg);
            CP_WAIT0();
            __syncthreads();
        }

        float* lg = (float*)smem;
        {
            const int r0 = lane >> 2;
            const int c0 = (lane & 3) * 2;
            const float inv = 1.0f / 2048.0f;
#pragma unroll
            for (int mt = 0; mt < 2; mt++)
#pragma unroll
                for (int nt = 0; nt < 8; nt++) {
                    int row = wm + mt * 16 + r0;
                    int col = wn + nt * 8 + c0;
                    __half2 h01 = *(__half2*)&acc2[mt][nt][0];
                    __half2 h23 = *(__half2*)&acc2[mt][nt][1];
                    lg[(size_t)row * (NEXP + 1) + col]           = acc1[mt][nt][0] + __low2float (h01) * inv;
                    lg[(size_t)row * (NEXP + 1) + col + 1]       = acc1[mt][nt][1] + __high2float(h01) * inv;
                    lg[(size_t)(row + 8) * (NEXP + 1) + col]     = acc1[mt][nt][2] + __low2float (h23) * inv;
                    lg[(size_t)(row + 8) * (NEXP + 1) + col + 1] = acc1[mt][nt][3] + __high2float(h23) * inv;
                }
        }
        __syncthreads();

        if (tid < BM)
            topk_scan(lg + (size_t)tid * (NEXP + 1), bm + tid, T, out);

    } else {
        // ================= FP32 ROLE (exact FFMA2 GEMM) =================
        const int rf = grp * NF_PER + (rem - NT_PER);
        const int fbase = TENSOR_TOKENS + rf * FM;

        float* xs = (float*)smem;                 // [2][16][64] (slotted rows)
        float* wsm = (float*)(smem + 8192);       // [2][16][128]

        const int ty = tid >> 4;                  // 0..7  (6 tokens each)
        const int tx = tid & 15;                  // 0..15 (8 experts each)

        unsigned long long acc[6][4];
#pragma unroll
        for (int i = 0; i < 6; i++)
#pragma unroll
            for (int j = 0; j < 4; j++) acc[i][j] = 0ull;

        const float* xg = x + (size_t)fbase * HDIM;

        // loaders: x 192 float4/chunk, w 512 float4/chunk
        float4 xv[2], wv[4];

#define F_LOAD(c) do {                                                         \
        if (tid < 64) {                                                        \
            int f = tid + 128;                                                 \
            xv[1] = *(const float4*)(xg + (size_t)(f >> 2) * HDIM + (c) * FBK + (f & 3) * 4); \
        }                                                                      \
        xv[0] = *(const float4*)(xg + (size_t)(tid >> 2) * HDIM + (c) * FBK + (tid & 3) * 4); \
        _Pragma("unroll")                                                      \
        for (int j = 0; j < 4; j++) {                                          \
            int f = tid + j * 128;                                             \
            wv[j] = *(const float4*)(w + (size_t)(f >> 2) * HDIM + (c) * FBK + (f & 3) * 4); \
        }                                                                      \
} while (0)

#define F_STORE(s) do {                                                        \
        {                                                                      \
            int f = tid, row = f >> 2, q = f & 3;                              \
            int slot = (row / 6) * 8 + (row % 6);                              \
            xs[FXS(s)/4 + (q * 4 + 0) * 64 + slot] = xv[0].x;                  \
            xs[FXS(s)/4 + (q * 4 + 1) * 64 + slot] = xv[0].y;                  \
            xs[FXS(s)/4 + (q * 4 + 2) * 64 + slot] = xv[0].z;                  \
            xs[FXS(s)/4 + (q * 4 + 3) * 64 + slot] = xv[0].w;                  \
        }                                                                      \
        if (tid < 64) {                                                        \
            int f = tid + 128, row = f >> 2, q = f & 3;                        \
            int slot = (row / 6) * 8 + (row % 6);                              \
            xs[FXS(s)/4 + (q * 4 + 0) * 64 + slot] = xv[1].x;                  \
            xs[FXS(s)/4 + (q * 4 + 1) * 64 + slot] = xv[1].y;                  \
            xs[FXS(s)/4 + (q * 4 + 2) * 64 + slot] = xv[1].z;                  \
            xs[FXS(s)/4 + (q * 4 + 3) * 64 + slot] = xv[1].w;                  \
        }                                                                      \
        _Pragma("unroll")                                                      \
        for (int j = 0; j < 4; j++) {                                          \
            int f = tid + j * 128, row = f >> 2, q = f & 3;                    \
            wsm[(FWS(s)-8192)/4 + (q * 4 + 0) * 128 + row] = wv[j].x;          \
            wsm[(FWS(s)-8192)/4 + (q * 4 + 1) * 128 + row] = wv[j].y;          \
            wsm[(FWS(s)-8192)/4 + (q * 4 + 2) * 128 + row] = wv[j].z;          \
            wsm[(FWS(s)-8192)/4 + (q * 4 + 3) * 128 + row] = wv[j].w;          \
        }                                                                      \
} while (0)

        F_LOAD(0);
        F_STORE(0);
        __syncthreads();

        for (int c = 0; c < FNCH; c++) {
            const int s  = c & 1;
            const int ns = s ^ 1;
            if (c + 1 < FNCH) F_LOAD(c + 1);

#pragma unroll
            for (int k = 0; k < FBK; k++) {
                const float* xrow = xs + FXS(s)/4 + k * 64 + ty * 8;
                float4 a03 = *(const float4*)xrow;
                float2 a45 = *(const float2*)(xrow + 4);
                const float* wrow = wsm + (FWS(s)-8192)/4 + k * 128 + tx * 8;
                ulonglong2 b01 = *(const ulonglong2*)wrow;
                ulonglong2 b23 = *(const ulonglong2*)(wrow + 4);
                unsigned long long ap[6];
                PACK2(ap[0], a03.x); PACK2(ap[1], a03.y); PACK2(ap[2], a03.z);
                PACK2(ap[3], a03.w); PACK2(ap[4], a45.x); PACK2(ap[5], a45.y);
#pragma unroll
                for (int i = 0; i < 6; i++) {
                    FMA2(acc[i][0], ap[i], b01.x);
                    FMA2(acc[i][1], ap[i], b01.y);
                    FMA2(acc[i][2], ap[i], b23.x);
                    FMA2(acc[i][3], ap[i], b23.y);
                }
            }

            if (c + 1 < FNCH) F_STORE(ns);
            __syncthreads();
        }

        // spill logits [48][129]
        float* lg = (float*)smem;
#pragma unroll
        for (int i = 0; i < 6; i++) {
            float* row = lg + (size_t)(ty * 6 + i) * (NEXP + 1) + tx * 8;
#pragma unroll
            for (int j = 0; j < 4; j++) {
                float lo, hi;
                UNPACK2(lo, hi, acc[i][j]);
                row[2 * j]     = lo;
                row[2 * j + 1] = hi;
            }
        }
        __syncthreads();

        if (tid < FM)
            topk_scan(lg + (size_t)tid * (NEXP + 1), fbase + tid, T, out);
    }
}

extern "C" void kernel_launch(void* const* d_in, const int* in_sizes, int n_in,
                              void* d_out, int out_size)
{
    const float* x = (const float*)d_in[0];   // [4,4096,2048] fp32
    const float* w = (const float*)d_in[1];   // [128,2048]    fp32
    float* out = (float*)d_out;

    const int T = in_sizes[0] / HDIM;         // 16384

    prep_w_kernel<<<(NEXP * HDIM / 4) / 256, 256>>>(w);

    cudaFuncSetAttribute(gate_kernel,
                         cudaFuncAttributeMaxDynamicSharedMemorySize, SMEM_TOT);
    gate_kernel<<<PERIOD * NGROUP, NTHR, SMEM_TOT>>>(x, w, out, T);
}

// round 12
// speedup vs baseline: 3.7091x; 3.7091x over previous
#include <cuda_runtime.h>
#include <cuda_fp16.h>
#include <math.h>
#include <stdint.h>

// Qwen3 MoE gate: 1-pass fp16 mma.sync GEMM (approx logits, sigma~4e-4)
// + per-token top-12 scan + exact fp32 recompute of only near-tie candidates
// (gap < THETA) via a shared task queue. Selection/order thus exact; weights
// use approx logits (abs tolerance ~7e-2 >> 5e-4 error).
// Output: [idx f32 (T*8) | weights (T*8)].

#define HDIM 2048
#define NEXP 128
#define BM   64
#define BK   64
#define NCH  (HDIM / BK)          // 32
#define NTHR 128
#define TOPK 8
#define NCAND 12
#define THETA 4e-3f

#define XTILE_B  (BM * 128)       // 8KB
#define WTILE_B  (NEXP * 128)     // 16KB
#define OFF_XH   0
#define OFF_WH   XTILE_B
#define STAGE_B  (XTILE_B + WTILE_B)   // 24KB
#define SMEM_TOT 49152                 // 2 stages (48KB); epilogue reuses

// epilogue smem layout (bytes)
#define EP_LG    0                      // [64][129] f32 = 33024
#define EP_CID   33024                  // [64][12] int  = 3072
#define EP_CV    36096                  // [64][12] f32  = 3072
#define EP_TASK  39168                  // [768] u32     = 3072
#define EP_CNT   42240                  // int

__device__ __half g_wh[NEXP * HDIM];

__device__ __forceinline__ uint32_t smem_u32(const void* p) {
    uint32_t a;
    asm("{ .reg .u64 t; cvta.to.shared.u64 t, %1; cvt.u32.u64 %0, t; }"
        : "=r"(a) : "l"(p));
    return a;
}

#define SWZ(o) ((o) ^ ((((uint32_t)(o)) >> 3) & 0x70))

#define CP16(dst, src) \
    asm volatile("cp.async.cg.shared.global [%0], [%1], 16;" \
                 :: "r"(dst), "l"(src))
#define CP_COMMIT() asm volatile("cp.async.commit_group;" ::: "memory")
#define CP_WAIT0()  asm volatile("cp.async.wait_group 0;" ::: "memory")

#define LDM4(R, a) \
    asm volatile("ldmatrix.sync.aligned.m8n8.x4.shared.b16 {%0,%1,%2,%3}, [%4];" \
                 : "=r"((R)[0]), "=r"((R)[1]), "=r"((R)[2]), "=r"((R)[3])      \
                 : "r"(a))

#define MMA(d, a, b0, b1) \
    asm volatile("mma.sync.aligned.m16n8k16.row.col.f32.f16.f16.f32 "          \
                 "{%0,%1,%2,%3}, {%4,%5,%6,%7}, {%8,%9}, {%0,%1,%2,%3};"       \
                 : "+f"((d)[0]), "+f"((d)[1]), "+f"((d)[2]), "+f"((d)[3])      \
                 : "r"((a)[0]), "r"((a)[1]), "r"((a)[2]), "r"((a)[3]),         \
                   "r"(b0), "r"(b1))

#define FMA2(c, a, b) asm("fma.rn.f32x2 %0, %1, %2, %0;" : "+l"(c) : "l"(a), "l"(b))
#define UNPACK2(lo, hi, s) asm("mov.b64 {%0, %1}, %2;" : "=f"(lo), "=f"(hi) : "l"(s))

__device__ __forceinline__ uint32_t pack_h2(float a, float b) {
    __half2 h = __floats2half2_rn(a, b);
    return *(uint32_t*)&h;
}

// -------- prep: W -> fp16 --------
__global__ void prep_w_kernel(const float* __restrict__ w) {
    int i = blockIdx.x * blockDim.x + threadIdx.x;      // float4 index
    float4 v = ((const float4*)w)[i];
    uint2 hi;
    hi.x = pack_h2(v.x, v.y);
    hi.y = pack_h2(v.z, v.w);
    ((uint2*)g_wh)[i] = hi;
}

// -------- main fused kernel --------
__global__ __launch_bounds__(NTHR, 2)
void gate_kernel(const float* __restrict__ x, const float* __restrict__ w,
                 float* __restrict__ out, int T)
{
    extern __shared__ char smem[];
    const uint32_t sb = smem_u32(smem);
    const int tid  = threadIdx.x;
    const int lane = tid & 31;
    const int wid  = tid >> 5;
    const int bm   = blockIdx.x * BM;

    float acc1[2][8][4];
#pragma unroll
    for (int i = 0; i < 2; i++)
#pragma unroll
        for (int j = 0; j < 8; j++)
#pragma unroll
            for (int r = 0; r < 4; r++) acc1[i][j][r] = 0.f;

    int xrow[8];
#pragma unroll
    for (int j = 0; j < 8; j++) xrow[j] = (tid + j * NTHR) >> 4;
    const int xq = tid & 15;
    const float* xg = x + (size_t)bm * HDIM;

    int wrow[8];
#pragma unroll
    for (int j = 0; j < 8; j++) wrow[j] = (tid + j * NTHR) >> 3;
    const int ws = tid & 7;

    const int wm = (wid & 1) * 32;
    const int wn = (wid >> 1) * 64;
    const int aRow = (lane & 7) + ((lane >> 3) & 1) * 8;
    const int aKB  = ((lane >> 4) & 1) * 16;
    const int bRow = (lane & 7) + ((lane >> 4) & 1) * 8;
    const int bKB  = ((lane >> 3) & 1) * 16;

#define ISSUE_W(c, stg) do {                                                   \
    _Pragma("unroll")                                                          \
    for (int j = 0; j < 8; j++) {                                              \
        uint32_t o  = SWZ((uint32_t)(wrow[j] * 128 + ws * 16));                \
        const __half* sh = g_wh + (size_t)wrow[j] * HDIM + (c) * BK + ws * 8;  \
        CP16(sb + (stg) + OFF_WH + o, sh);                                     \
    }                                                                          \
    CP_COMMIT();                                                               \
} while (0)

#define LOAD_X(c, xr) do {                                                     \
    _Pragma("unroll")                                                          \
    for (int j = 0; j < 8; j++)                                                \
        xr[j] = *(const float4*)(xg + (size_t)xrow[j] * HDIM + (c) * BK + xq * 4); \
} while (0)

#define STORE_X(xr, stg) do {                                                  \
    _Pragma("unroll")                                                          \
    for (int j = 0; j < 8; j++) {                                              \
        float4 v = xr[j];                                                      \
        uint2 hi;                                                              \
        hi.x = pack_h2(v.x, v.y);  hi.y = pack_h2(v.z, v.w);                   \
        uint32_t o = SWZ((uint32_t)(xrow[j] * 128 + xq * 8));                  \
        *(uint2*)(smem + (stg) + OFF_XH + o) = hi;                             \
    }                                                                          \
} while (0)

    // ---- prologue ----
    {
        float4 xr[8];
        ISSUE_W(0, 0);
        LOAD_X(0, xr);
        STORE_X(xr, 0);
        CP_WAIT0();
        __syncthreads();
    }

    // ---- mainloop ----
    for (int c = 0; c < NCH; c++) {
        const uint32_t stg  = (uint32_t)((c & 1) ? STAGE_B : 0);
        const uint32_t nstg = stg ^ STAGE_B;
        float4 xr[8];
        if (c + 1 < NCH) {
            ISSUE_W(c + 1, nstg);
            LOAD_X(c + 1, xr);
        }

#pragma unroll
        for (int ks = 0; ks < 4; ks++) {
            uint32_t Ah[2][4], Bh[4][4];
#pragma unroll
            for (int mt = 0; mt < 2; mt++) {
                uint32_t o = SWZ((uint32_t)((wm + mt * 16 + aRow) * 128 + ks * 32 + aKB));
                LDM4(Ah[mt], sb + stg + OFF_XH + o);
            }
#pragma unroll
            for (int p = 0; p < 4; p++) {
                uint32_t o = SWZ((uint32_t)((wn + p * 16 + bRow) * 128 + ks * 32 + bKB));
                LDM4(Bh[p], sb + stg + OFF_WH + o);
            }
#pragma unroll
            for (int mt = 0; mt < 2; mt++)
#pragma unroll
                for (int nt = 0; nt < 8; nt++) {
                    const int p = nt >> 1, r0 = (nt & 1) * 2;
                    MMA(acc1[mt][nt], Ah[mt], Bh[p][r0], Bh[p][r0 + 1]);
                }
        }

        if (c + 1 < NCH) STORE_X(xr, nstg);
        CP_WAIT0();
        __syncthreads();
    }

    // ---- epilogue phase 1: spill approx logits [64][129] ----
    float* lg      = (float*)(smem + EP_LG);
    int*   cand_id = (int*)  (smem + EP_CID);
    float* cand_v  = (float*)(smem + EP_CV);
    uint32_t* tasks = (uint32_t*)(smem + EP_TASK);
    int*   task_cnt = (int*)(smem + EP_CNT);

    if (tid == 0) *task_cnt = 0;
    {
        const int r0 = lane >> 2;
        const int c0 = (lane & 3) * 2;
#pragma unroll
        for (int mt = 0; mt < 2; mt++)
#pragma unroll
            for (int nt = 0; nt < 8; nt++) {
                int row = wm + mt * 16 + r0;
                int col = wn + nt * 8 + c0;
                lg[(size_t)row * (NEXP + 1) + col]           = acc1[mt][nt][0];
                lg[(size_t)row * (NEXP + 1) + col + 1]       = acc1[mt][nt][1];
                lg[(size_t)(row + 8) * (NEXP + 1) + col]     = acc1[mt][nt][2];
                lg[(size_t)(row + 8) * (NEXP + 1) + col + 1] = acc1[mt][nt][3];
            }
    }
    __syncthreads();

    // ---- phase 2: per-token top-12 scan + near-tie task enqueue ----
    if (tid < BM) {
        float* row = lg + (size_t)tid * (NEXP + 1);
        float cv[NCAND];
        int   cid[NCAND];
#pragma unroll
        for (int j = 0; j < NCAND; j++) {
            float best = -INFINITY;
            int   bi   = 0;
#pragma unroll 8
            for (int c = 0; c < NEXP; c++) {
                float v = row[c];
                if (v > best) { best = v; bi = c; }    // tie -> lowest index
            }
            row[bi] = -INFINITY;
            cv[j] = best; cid[j] = bi;
            cand_v [tid * NCAND + j] = best;
            cand_id[tid * NCAND + j] = bi;
        }
        // mark adjacent near-ties (descending sorted)
        unsigned need = 0;
#pragma unroll
        for (int j = 0; j < NCAND - 1; j++)
            if (cv[j] - cv[j + 1] < THETA) need |= (3u << j);   // j and j+1
#pragma unroll
        for (int j = 0; j < NCAND; j++)
            if (need & (1u << j)) {
                int s = atomicAdd(task_cnt, 1);
                tasks[s] = ((uint32_t)tid << 8) | (uint32_t)j;
            }
        (void)cid;
    }
    __syncthreads();

    // ---- phase 3: exact fp32 recompute of queued (token, slot) ----
    {
        const int n = *task_cnt;
        for (int i = wid; i < n; i += 4) {
            uint32_t tk = tasks[i];
            const int t = tk >> 8, j = tk & 255;
            const int e = cand_id[t * NCAND + j];
            const float* xr = x + (size_t)(bm + t) * HDIM + lane * 4;
            const float* wr = w + (size_t)e * HDIM + lane * 4;
            unsigned long long acc = 0ull;
#pragma unroll
            for (int it = 0; it < 16; it++) {
                ulonglong2 xv = *(const ulonglong2*)(xr + it * 128);
                ulonglong2 wv = *(const ulonglong2*)(wr + it * 128);
                FMA2(acc, xv.x, wv.x);
                FMA2(acc, xv.y, wv.y);
            }
            float lo, hi;
            UNPACK2(lo, hi, acc);
            float s = lo + hi;
#pragma unroll
            for (int o = 16; o; o >>= 1)
                s += __shfl_xor_sync(0xffffffffu, s, o);
            if (lane == 0) cand_v[t * NCAND + j] = s;
        }
    }
    __syncthreads();

    // ---- phase 4: final top-8 over 12 candidates, softmax, output ----
    if (tid < BM) {
        float cv[NCAND];
        int   cid[NCAND];
#pragma unroll
        for (int j = 0; j < NCAND; j++) {
            cv[j]  = cand_v [tid * NCAND + j];
            cid[j] = cand_id[tid * NCAND + j];
        }
        unsigned used = 0;
        int   ids[TOPK];
        float vals[TOPK];
#pragma unroll
        for (int kk = 0; kk < TOPK; kk++) {
            float best = -INFINITY;
            int   bj = 0, bid = NEXP;
#pragma unroll
            for (int j = 0; j < NCAND; j++) {
                if (used & (1u << j)) continue;
                float v = cv[j];
                int   id = cid[j];
                if (v > best || (v == best && id < bid)) {
                    best = v; bj = j; bid = id;
                }
            }
            used |= (1u << bj);
            ids[kk]  = bid;
            vals[kk] = best;
        }
        const float m0 = vals[0];
        float wts[TOPK], sum = 0.f;
#pragma unroll
        for (int kk = 0; kk < TOPK; kk++) {
            float e = expf(vals[kk] - m0);
            wts[kk] = e;
            sum += e;
        }
        const int token = bm + tid;
        float* out_idx = out;
        float* out_wt  = out + (size_t)T * TOPK;
#pragma unroll
        for (int kk = 0; kk < TOPK; kk++) {
            out_idx[(size_t)token * TOPK + kk] = (float)ids[kk];
            out_wt [(size_t)token * TOPK + kk] = wts[kk] / sum;
        }
    }
}

extern "C" void kernel_launch(void* const* d_in, const int* in_sizes, int n_in,
                              void* d_out, int out_size)
{
    const float* x = (const float*)d_in[0];   // [4,4096,2048] fp32
    const float* w = (const float*)d_in[1];   // [128,2048]    fp32
    float* out = (float*)d_out;

    const int T = in_sizes[0] / HDIM;         // 16384

    prep_w_kernel<<<(NEXP * HDIM / 4) / 256, 256>>>(w);

    cudaFuncSetAttribute(gate_kernel,
                         cudaFuncAttributeMaxDynamicSharedMemorySize, SMEM_TOT);
    gate_kernel<<<T / BM, NTHR, SMEM_TOT>>>(x, w, out, T);
}